// round 12
// baseline (speedup 1.0000x reference)
#include <cuda_runtime.h>
#include <cuda_fp16.h>
#include <cstdint>
#include <cstddef>

#define BB   8
#define NN   2048
#define FIN  256
#define FOUT 64
#define ALPHA 0.2f
#define ROWS_TOT (BB * NN)

// ---------------- scratch (device globals: allocation-free) ----------------
__device__ float2 g_thR[ROWS_TOT];                   // (-sb_i, exp((a-1)*sb_i))
__device__ float4 g_EEd[ROWS_TOT];                   // (exp(d_j), exp(a*d_j), d_j, 0)
// h transposed fp16, [b][feat][j], j stored 32-chunk INTERLEAVED:
//   pos(j) = (j&~31) + q*8 + kk*4 + half*2 + elem
__device__ unsigned short g_hhT[BB * FOUT * NN];

// ---------------- helpers ----------------
static __device__ __forceinline__ uint32_t cvt2h(float lo, float hi) {
    uint32_t d;
    asm("cvt.rn.f16x2.f32 %0, %1, %2;" : "=r"(d) : "f"(hi), "f"(lo));
    return d;
}
static __device__ __forceinline__ float h_lo(uint32_t w) {
    return __half2float(__ushort_as_half((unsigned short)(w & 0xffffu)));
}
static __device__ __forceinline__ float h_hi(uint32_t w) {
    return __half2float(__ushort_as_half((unsigned short)(w >> 16)));
}

static __device__ __forceinline__ void mma16816h(float* c, const uint32_t* a,
                                                 uint32_t b0, uint32_t b1) {
    asm volatile(
        "mma.sync.aligned.m16n8k16.row.col.f32.f16.f16.f32 "
        "{%0,%1,%2,%3}, {%4,%5,%6,%7}, {%8,%9}, {%0,%1,%2,%3};"
        : "+f"(c[0]), "+f"(c[1]), "+f"(c[2]), "+f"(c[3])
        : "r"(a[0]), "r"(a[1]), "r"(a[2]), "r"(a[3]), "r"(b0), "r"(b1));
}

// ============================================================================
// Kernel 1: h = x @ W + b_W via mma.sync fp16 (2-term: ah*bh + ah*bl).
// 128 threads, 64 rows/CTA, grid 256. Epilogue buffer aliases W-prepack smem.
// ============================================================================
#define LIN_SW_BYTES 32768
#define LIN_HB_STRIDE 68
#define LIN_SMEM (2 * LIN_SW_BYTES)

__global__ __launch_bounds__(128, 3) void k_linear(
    const float* __restrict__ x, const float* __restrict__ W,
    const float* __restrict__ bW, const float* __restrict__ a_src,
    const float* __restrict__ a_dst, const float* __restrict__ a_b)
{
    extern __shared__ __align__(16) unsigned char lsm[];
    uint32_t* WH32 = (uint32_t*)lsm;
    uint32_t* WL32 = (uint32_t*)(lsm + LIN_SW_BYTES);
    float*    hbuf = (float*)lsm;                     // alias (post-mainloop)

    const int t    = threadIdx.x;
    const int w    = t >> 5;
    const int lane = t & 31;
    const int q    = lane & 3;
    const int r    = lane >> 2;
    const int i0   = blockIdx.x * 64;
    const float ab = a_b[0];

    // ---- prepack W into fragment-order fp16 hi/lo ----
#pragma unroll
    for (int i = 0; i < 64; i++) {
        int u    = t + 128 * i;
        int half = u & 1;
        int qq   = (u >> 1) & 3;
        int n    = (u >> 3) & 63;
        int ks   = u >> 9;
        int k0   = ks * 16 + half * 8 + 2 * qq;
        float w0 = W[(size_t)k0 * FOUT + n];
        float w1 = W[(size_t)(k0 + 1) * FOUT + n];
        uint32_t hi = cvt2h(w0, w1);
        WH32[u] = hi;
        WL32[u] = cvt2h(w0 - h_lo(hi), w1 - h_hi(hi));
    }
    __syncthreads();

    const float* xA = x + (size_t)(i0 + w * 16 + r) * FIN;
    const float* xB = xA + (size_t)8 * FIN;

    float c[8][4];
#pragma unroll
    for (int n = 0; n < 8; n++)
#pragma unroll
        for (int k = 0; k < 4; k++) c[n][k] = 0.0f;

    float2 xb[2][4];
    xb[0][0] = *(const float2*)(xA + 2 * q);
    xb[0][1] = *(const float2*)(xB + 2 * q);
    xb[0][2] = *(const float2*)(xA + 8 + 2 * q);
    xb[0][3] = *(const float2*)(xB + 8 + 2 * q);

#pragma unroll
    for (int ks = 0; ks < 16; ks++) {
        const int cur = ks & 1;
        if (ks + 1 < 16) {
            const int kb = (ks + 1) * 16;
            xb[cur ^ 1][0] = *(const float2*)(xA + kb + 2 * q);
            xb[cur ^ 1][1] = *(const float2*)(xB + kb + 2 * q);
            xb[cur ^ 1][2] = *(const float2*)(xA + kb + 8 + 2 * q);
            xb[cur ^ 1][3] = *(const float2*)(xB + kb + 8 + 2 * q);
        }

        uint32_t ah[4];
#pragma unroll
        for (int e = 0; e < 4; e++) {
            float2 xv = xb[cur][e];
            ah[e] = cvt2h(xv.x, xv.y);
        }

#pragma unroll
        for (int nt = 0; nt < 8; nt++) {
            int slot = (ks * 64 + nt * 8 + r) * 4 + q;
            uint2 bh = *(const uint2*)&WH32[slot * 2];
            uint2 bl = *(const uint2*)&WL32[slot * 2];
            mma16816h(c[nt], ah, bh.x, bh.y);
            mma16816h(c[nt], ah, bl.x, bl.y);
        }
    }

    // ---- stash c to (aliased) smem ----
    __syncthreads();
    {
        float* hbA = hbuf + (w * 16 + r) * LIN_HB_STRIDE;
        float* hbB = hbA + 8 * LIN_HB_STRIDE;
#pragma unroll
        for (int nt = 0; nt < 8; nt++) {
            *(float2*)(hbA + nt * 8 + 2 * q) = make_float2(c[nt][0], c[nt][1]);
            *(float2*)(hbB + nt * 8 + 2 * q) = make_float2(c[nt][2], c[nt][3]);
        }
    }
    __syncthreads();

    // ---- epilogue ----
    const int fc = t & 15;
    const int rw = t >> 4;
    float4 bw4 = *(const float4*)&bW[fc * 4];
    float4 as4 = *(const float4*)&a_src[fc * 4];
    float4 ad4 = *(const float4*)&a_dst[fc * 4];

    float hv[8][4];
    float sp[8], dp[8];
#pragma unroll
    for (int e = 0; e < 8; e++) {
        float4 v = *(const float4*)&hbuf[(rw * 8 + e) * LIN_HB_STRIDE + fc * 4];
        hv[e][0] = v.x + bw4.x; hv[e][1] = v.y + bw4.y;
        hv[e][2] = v.z + bw4.z; hv[e][3] = v.w + bw4.w;
        sp[e] = hv[e][0] * as4.x + hv[e][1] * as4.y + hv[e][2] * as4.z + hv[e][3] * as4.w;
        dp[e] = hv[e][0] * ad4.x + hv[e][1] * ad4.y + hv[e][2] * ad4.z + hv[e][3] * ad4.w;
    }
#pragma unroll
    for (int o = 1; o < 16; o <<= 1) {
#pragma unroll
        for (int e = 0; e < 8; e++) {
            sp[e] += __shfl_xor_sync(0xffffffffu, sp[e], o);
            dp[e] += __shfl_xor_sync(0xffffffffu, dp[e], o);
        }
    }
    if (fc == 0) {
#pragma unroll
        for (int e = 0; e < 8; e++) {
            int row = i0 + rw * 8 + e;
            float sb = sp[e] + ab;
            g_thR[row] = make_float2(-sb, expf((ALPHA - 1.0f) * sb));
            g_EEd[row] = make_float4(expf(dp[e]), expf(ALPHA * dp[e]), dp[e], 0.0f);
        }
    }

    // ---- transposed fp16 stores, 32-chunk INTERLEAVED order ----
    const int    jb    = (i0 & (NN - 1)) + rw * 8;
    const size_t plane = (size_t)(i0 >> 11) * FOUT;
    const int    ibase = (jb & ~31) + (((jb >> 4) & 1) << 2) + (((jb >> 3) & 1) << 1);
#pragma unroll
    for (int ff = 0; ff < 4; ff++) {
        int f = fc * 4 + ff;
        size_t rowb = (plane + f) * NN + ibase;
#pragma unroll
        for (int p2 = 0; p2 < 4; p2++) {
            float v0 = hv[p2 * 2][ff], v1 = hv[p2 * 2 + 1][ff];
            *(uint32_t*)&g_hhT[rowb + p2 * 8] = cvt2h(v0, v1);
        }
    }
}

// ============================================================================
// Kernel 2: fused masked softmax-weight P@h, INTRA-CTA split-K.
// Grid (32, 8) x 256 threads: 64 i-rows/CTA; warps 0-3 j in [0,1024),
// warps 4-7 j in [1024,2048). Partials meet in smem; normalize+ELU+store
// done by warps 0-3. No global partials, no finalize kernel.
// ============================================================================
#define NCH 32                 // chunks per half

__global__ __launch_bounds__(256, 2) void k_attn4(
    const int* __restrict__ adj, float* __restrict__ out)
{
    __shared__ __align__(16) uint8_t sBH[2][2][FOUT * 64];  // [half][stage] 4KB
    __shared__ float4 sEE[2][2][32];
    __shared__ float  cred[64 * 68];                        // 17.4 KB
    __shared__ float  lred[64];

    const int t    = threadIdx.x;
    const int wid  = t >> 5;
    const int lane = t & 31;
    const int q    = lane & 3;
    const int r    = lane >> 2;
    const int half = wid >> 2;          // j-half
    const int wq   = wid & 3;           // row group
    const int b    = blockIdx.y;
    const int i0   = blockIdx.x * 64;
    const int ch0  = half * NCH;        // global chunk base for this half

    const int iA = i0 + wq * 16 + r;
    const int iB = iA + 8;
    const size_t bNN = (size_t)b * NN;

    const float2 tA = g_thR[bNN + iA];
    const float2 tB = g_thR[bNN + iB];
    const int* aA = adj + bNN * NN + (size_t)iA * NN + 2 * q;
    const int* aB = aA + 8 * NN;

    float c[8][4];
#pragma unroll
    for (int n = 0; n < 8; n++)
#pragma unroll
        for (int k = 0; k < 4; k++) c[n][k] = 0.0f;
    float laccA = 0.0f, laccB = 0.0f;

    // fill roles: this thread fills ITS half's buffers; 128 threads/half,
    // each covers 2 q-slots (2 x uint4 per chunk).
    const int t7    = t & 127;
    const int featf = t7 >> 1;
    const int qgf   = (t7 & 1) * 2;
    const unsigned short* hhpf = g_hhT + ((size_t)b * FOUT + featf) * NN + qgf * 8;
    const uint32_t sOff = (uint32_t)featf * 64 + (uint32_t)qgf * 16;

    // prologue: stage 0 for this half + adj preload
    {
        const int cg = ch0;
        *(uint4*)&sBH[half][0][sOff]      = *(const uint4*)(hhpf + cg * 32);
        *(uint4*)&sBH[half][0][sOff + 16] = *(const uint4*)(hhpf + cg * 32 + 8);
        if (t7 < 32) sEE[half][0][t7] = g_EEd[bNN + cg * 32 + t7];
    }
    int2 mC[8];
#pragma unroll
    for (int kk = 0; kk < 2; kk++) {
        const int jo = ch0 * 32 + kk * 16;
        mC[kk * 4 + 0] = *(const int2*)(aA + jo);
        mC[kk * 4 + 1] = *(const int2*)(aA + jo + 8);
        mC[kk * 4 + 2] = *(const int2*)(aB + jo);
        mC[kk * 4 + 3] = *(const int2*)(aB + jo + 8);
    }
    __syncthreads();

    const uint32_t tb = (uint32_t)r * 64 + (uint32_t)q * 16;

    uint4 pf0, pf1; float4 pf_e;
#pragma unroll 1
    for (int cl = 0; cl < NCH; cl++) {
        const int s = cl & 1;

        int2 mN[8];
        if (cl + 1 < NCH) {
            const int cg = ch0 + cl + 1;
            pf0 = *(const uint4*)(hhpf + cg * 32);
            pf1 = *(const uint4*)(hhpf + cg * 32 + 8);
            if (t7 < 32) pf_e = g_EEd[bNN + cg * 32 + t7];
#pragma unroll
            for (int kk = 0; kk < 2; kk++) {
                const int jo = cg * 32 + kk * 16;
                mN[kk * 4 + 0] = *(const int2*)(aA + jo);
                mN[kk * 4 + 1] = *(const int2*)(aA + jo + 8);
                mN[kk * 4 + 2] = *(const int2*)(aB + jo);
                mN[kk * 4 + 3] = *(const int2*)(aB + jo + 8);
            }
        }

        // ---- A fragments from buffered adj + sEE ----
        uint32_t ah[2][4];
#pragma unroll
        for (int kk = 0; kk < 2; kk++) {
            const int jl = kk * 16 + 2 * q;
            float4 eA0 = sEE[half][s][jl];
            float4 eA1 = sEE[half][s][jl + 1];
            float4 eB0 = sEE[half][s][jl + 8];
            float4 eB1 = sEE[half][s][jl + 9];
            int2 mAa = mC[kk * 4 + 0];
            int2 mAb = mC[kk * 4 + 1];
            int2 mBa = mC[kk * 4 + 2];
            int2 mBb = mC[kk * 4 + 3];

            float pAa0 = (eA0.z >= tA.x) ? eA0.x : tA.y * eA0.y; if (mAa.x == 0) pAa0 = 0.0f;
            float pAa1 = (eA1.z >= tA.x) ? eA1.x : tA.y * eA1.y; if (mAa.y == 0) pAa1 = 0.0f;
            float pAb0 = (eB0.z >= tA.x) ? eB0.x : tA.y * eB0.y; if (mAb.x == 0) pAb0 = 0.0f;
            float pAb1 = (eB1.z >= tA.x) ? eB1.x : tA.y * eB1.y; if (mAb.y == 0) pAb1 = 0.0f;
            float pBa0 = (eA0.z >= tB.x) ? eA0.x : tB.y * eA0.y; if (mBa.x == 0) pBa0 = 0.0f;
            float pBa1 = (eA1.z >= tB.x) ? eA1.x : tB.y * eA1.y; if (mBa.y == 0) pBa1 = 0.0f;
            float pBb0 = (eB0.z >= tB.x) ? eB0.x : tB.y * eB0.y; if (mBb.x == 0) pBb0 = 0.0f;
            float pBb1 = (eB1.z >= tB.x) ? eB1.x : tB.y * eB1.y; if (mBb.y == 0) pBb1 = 0.0f;

            laccA += (pAa0 + pAa1) + (pAb0 + pAb1);
            laccB += (pBa0 + pBa1) + (pBb0 + pBb1);

            ah[kk][0] = cvt2h(pAa0, pAa1);
            ah[kk][1] = cvt2h(pBa0, pBa1);
            ah[kk][2] = cvt2h(pAb0, pAb1);
            ah[kk][3] = cvt2h(pBb0, pBb1);
        }

        // ---- mma: 8 n-tiles, one LDS.128 each ----
#pragma unroll
        for (int n = 0; n < 8; n++) {
            uint4 bh = *(const uint4*)&sBH[half][s][(uint32_t)n * 512 + tb];
            mma16816h(c[n], ah[0], bh.x, bh.y);
            mma16816h(c[n], ah[1], bh.z, bh.w);
        }

        if (cl + 1 < NCH) {
            *(uint4*)&sBH[half][s ^ 1][sOff]      = pf0;
            *(uint4*)&sBH[half][s ^ 1][sOff + 16] = pf1;
            if (t7 < 32) sEE[half][s ^ 1][t7] = pf_e;
#pragma unroll
            for (int u = 0; u < 8; u++) mC[u] = mN[u];
        }
        __syncthreads();
    }

    // ---- intra-CTA split-K reduction ----
    laccA += __shfl_xor_sync(0xffffffffu, laccA, 1);
    laccA += __shfl_xor_sync(0xffffffffu, laccA, 2);
    laccB += __shfl_xor_sync(0xffffffffu, laccB, 1);
    laccB += __shfl_xor_sync(0xffffffffu, laccB, 2);

    const int rl = wq * 16 + r;
    if (half == 1) {
        float* cr  = cred + rl * 68 + 2 * q;
        float* cr2 = cred + (rl + 8) * 68 + 2 * q;
#pragma unroll
        for (int n = 0; n < 8; n++) {
            *(float2*)(cr  + n * 8) = make_float2(c[n][0], c[n][1]);
            *(float2*)(cr2 + n * 8) = make_float2(c[n][2], c[n][3]);
        }
        if (q == 0) { lred[rl] = laccA; lred[rl + 8] = laccB; }
    }
    __syncthreads();

    if (half == 0) {
        const float liA = 1.0f / (laccA + lred[rl]);
        const float liB = 1.0f / (laccB + lred[rl + 8]);
        const float* cr  = cred + rl * 68 + 2 * q;
        const float* cr2 = cred + (rl + 8) * 68 + 2 * q;
        float* opA = out + (bNN + i0 + rl) * FOUT + 2 * q;
        float* opB = opA + 8 * FOUT;
#pragma unroll
        for (int n = 0; n < 8; n++) {
            float v0 = (c[n][0] + cr[n * 8])      * liA;
            float v1 = (c[n][1] + cr[n * 8 + 1])  * liA;
            float v2 = (c[n][2] + cr2[n * 8])     * liB;
            float v3 = (c[n][3] + cr2[n * 8 + 1]) * liB;
            v0 = v0 > 0.0f ? v0 : expm1f(v0);
            v1 = v1 > 0.0f ? v1 : expm1f(v1);
            v2 = v2 > 0.0f ? v2 : expm1f(v2);
            v3 = v3 > 0.0f ? v3 : expm1f(v3);
            *(float2*)(opA + n * 8) = make_float2(v0, v1);
            *(float2*)(opB + n * 8) = make_float2(v2, v3);
        }
    }
}

// ============================================================================
extern "C" void kernel_launch(void* const* d_in, const int* in_sizes, int n_in,
                              void* d_out, int out_size)
{
    const float* x     = (const float*)d_in[0];
    const int*   adj   = (const int*)d_in[1];
    const float* W     = (const float*)d_in[2];
    const float* bW    = (const float*)d_in[3];
    const float* a_src = (const float*)d_in[4];
    const float* a_dst = (const float*)d_in[5];
    const float* a_b   = (const float*)d_in[6];
    float* out = (float*)d_out;
    (void)in_sizes; (void)n_in; (void)out_size;

    cudaFuncSetAttribute(k_linear, cudaFuncAttributeMaxDynamicSharedMemorySize,
                         LIN_SMEM);

    k_linear<<<ROWS_TOT / 64, 128, LIN_SMEM>>>(x, W, bW, a_src, a_dst, a_b);

    dim3 grid(NN / 64, BB);
    k_attn4<<<grid, 256>>>(adj, out);
}

// round 15
// speedup vs baseline: 1.0728x; 1.0728x over previous
#include <cuda_runtime.h>
#include <cuda_fp16.h>
#include <cstdint>
#include <cstddef>

#define BB   8
#define NN   2048
#define FIN  256
#define FOUT 64
#define ALPHA 0.2f
#define SPLIT 2
#define ROWS_TOT (BB * NN)

// ---------------- scratch (device globals: allocation-free) ----------------
__device__ uint32_t g_Rh[ROWS_TOT];        // half2(R_i, R_i), R = exp((a-1)sb)
__device__ uint32_t g_Epk[ROWS_TOT / 2];   // half2(E_{2p}, E_{2p+1}), E = exp(d)
__device__ uint32_t g_E2pk[ROWS_TOT / 2];  // half2(E2_{2p}, E2_{2p+1}), E2 = exp(a d)
// h transposed fp16, [b][feat][j], j stored 32-chunk INTERLEAVED:
//   pos(j) = (j&~31) + q*8 + kk*4 + half*2 + elem
__device__ unsigned short g_hhT[BB * FOUT * NN];
__device__ float g_pacc[SPLIT * ROWS_TOT * FOUT];    // 8 MB split-K partials
__device__ float g_pl[SPLIT * ROWS_TOT];

// ---------------- helpers ----------------
static __device__ __forceinline__ uint32_t cvt2h(float lo, float hi) {
    uint32_t d;
    asm("cvt.rn.f16x2.f32 %0, %1, %2;" : "=r"(d) : "f"(hi), "f"(lo));
    return d;
}
static __device__ __forceinline__ float h_lo(uint32_t w) {
    return __half2float(__ushort_as_half((unsigned short)(w & 0xffffu)));
}
static __device__ __forceinline__ float h_hi(uint32_t w) {
    return __half2float(__ushort_as_half((unsigned short)(w >> 16)));
}
static __device__ __forceinline__ __half2 u2h(uint32_t u) {
    __half2 h; *(uint32_t*)&h = u; return h;
}
static __device__ __forceinline__ uint32_t h2u(__half2 h) {
    return *(uint32_t*)&h;
}
// mask half2 (1.0/0.0) from two 0/1 ints
static __device__ __forceinline__ __half2 mask2(int mx, int my) {
    uint32_t r;
    asm("prmt.b32 %0, %1, %2, 0x5410;" : "=r"(r) : "r"(mx), "r"(my));
    return __hgt2(u2h(r), u2h(0u));
}

static __device__ __forceinline__ void mma16816h(float* c, const uint32_t* a,
                                                 uint32_t b0, uint32_t b1) {
    asm volatile(
        "mma.sync.aligned.m16n8k16.row.col.f32.f16.f16.f32 "
        "{%0,%1,%2,%3}, {%4,%5,%6,%7}, {%8,%9}, {%0,%1,%2,%3};"
        : "+f"(c[0]), "+f"(c[1]), "+f"(c[2]), "+f"(c[3])
        : "r"(a[0]), "r"(a[1]), "r"(a[2]), "r"(a[3]), "r"(b0), "r"(b1));
}

// ============================================================================
// Kernel 1: h = x @ W + b_W via mma.sync fp16 (2-term: ah*bh + ah*bl).
// 128 threads, 64 rows/CTA, grid 256. Epilogue buffer aliases W-prepack smem.
// Epilogue writes half2 tables (R, pre-paired E/E2) + transposed fp16 h.
// ============================================================================
#define LIN_SW_BYTES 32768
#define LIN_HB_STRIDE 68
#define LIN_SMEM (2 * LIN_SW_BYTES)

__global__ __launch_bounds__(128, 3) void k_linear(
    const float* __restrict__ x, const float* __restrict__ W,
    const float* __restrict__ bW, const float* __restrict__ a_src,
    const float* __restrict__ a_dst, const float* __restrict__ a_b)
{
    extern __shared__ __align__(16) unsigned char lsm[];
    uint32_t* WH32 = (uint32_t*)lsm;
    uint32_t* WL32 = (uint32_t*)(lsm + LIN_SW_BYTES);
    float*    hbuf = (float*)lsm;                     // alias (post-mainloop)

    const int t    = threadIdx.x;
    const int w    = t >> 5;
    const int lane = t & 31;
    const int q    = lane & 3;
    const int r    = lane >> 2;
    const int i0   = blockIdx.x * 64;
    const float ab = a_b[0];

    // ---- prepack W into fragment-order fp16 hi/lo ----
#pragma unroll
    for (int i = 0; i < 64; i++) {
        int u    = t + 128 * i;
        int half = u & 1;
        int qq   = (u >> 1) & 3;
        int n    = (u >> 3) & 63;
        int ks   = u >> 9;
        int k0   = ks * 16 + half * 8 + 2 * qq;
        float w0 = W[(size_t)k0 * FOUT + n];
        float w1 = W[(size_t)(k0 + 1) * FOUT + n];
        uint32_t hi = cvt2h(w0, w1);
        WH32[u] = hi;
        WL32[u] = cvt2h(w0 - h_lo(hi), w1 - h_hi(hi));
    }
    __syncthreads();

    const float* xA = x + (size_t)(i0 + w * 16 + r) * FIN;
    const float* xB = xA + (size_t)8 * FIN;

    float c[8][4];
#pragma unroll
    for (int n = 0; n < 8; n++)
#pragma unroll
        for (int k = 0; k < 4; k++) c[n][k] = 0.0f;

    float2 xb[2][4];
    xb[0][0] = *(const float2*)(xA + 2 * q);
    xb[0][1] = *(const float2*)(xB + 2 * q);
    xb[0][2] = *(const float2*)(xA + 8 + 2 * q);
    xb[0][3] = *(const float2*)(xB + 8 + 2 * q);

#pragma unroll
    for (int ks = 0; ks < 16; ks++) {
        const int cur = ks & 1;
        if (ks + 1 < 16) {
            const int kb = (ks + 1) * 16;
            xb[cur ^ 1][0] = *(const float2*)(xA + kb + 2 * q);
            xb[cur ^ 1][1] = *(const float2*)(xB + kb + 2 * q);
            xb[cur ^ 1][2] = *(const float2*)(xA + kb + 8 + 2 * q);
            xb[cur ^ 1][3] = *(const float2*)(xB + kb + 8 + 2 * q);
        }

        uint32_t ah[4];
#pragma unroll
        for (int e = 0; e < 4; e++) {
            float2 xv = xb[cur][e];
            ah[e] = cvt2h(xv.x, xv.y);
        }

#pragma unroll
        for (int nt = 0; nt < 8; nt++) {
            int slot = (ks * 64 + nt * 8 + r) * 4 + q;
            uint2 bh = *(const uint2*)&WH32[slot * 2];
            uint2 bl = *(const uint2*)&WL32[slot * 2];
            mma16816h(c[nt], ah, bh.x, bh.y);
            mma16816h(c[nt], ah, bl.x, bl.y);
        }
    }

    // ---- stash c to (aliased) smem ----
    __syncthreads();
    {
        float* hbA = hbuf + (w * 16 + r) * LIN_HB_STRIDE;
        float* hbB = hbA + 8 * LIN_HB_STRIDE;
#pragma unroll
        for (int nt = 0; nt < 8; nt++) {
            *(float2*)(hbA + nt * 8 + 2 * q) = make_float2(c[nt][0], c[nt][1]);
            *(float2*)(hbB + nt * 8 + 2 * q) = make_float2(c[nt][2], c[nt][3]);
        }
    }
    __syncthreads();

    // ---- epilogue ----
    const int fc = t & 15;
    const int rw = t >> 4;
    float4 bw4 = *(const float4*)&bW[fc * 4];
    float4 as4 = *(const float4*)&a_src[fc * 4];
    float4 ad4 = *(const float4*)&a_dst[fc * 4];

    float hv[8][4];
    float sp[8], dp[8];
#pragma unroll
    for (int e = 0; e < 8; e++) {
        float4 v = *(const float4*)&hbuf[(rw * 8 + e) * LIN_HB_STRIDE + fc * 4];
        hv[e][0] = v.x + bw4.x; hv[e][1] = v.y + bw4.y;
        hv[e][2] = v.z + bw4.z; hv[e][3] = v.w + bw4.w;
        sp[e] = hv[e][0] * as4.x + hv[e][1] * as4.y + hv[e][2] * as4.z + hv[e][3] * as4.w;
        dp[e] = hv[e][0] * ad4.x + hv[e][1] * ad4.y + hv[e][2] * ad4.z + hv[e][3] * ad4.w;
    }
#pragma unroll
    for (int o = 1; o < 16; o <<= 1) {
#pragma unroll
        for (int e = 0; e < 8; e++) {
            sp[e] += __shfl_xor_sync(0xffffffffu, sp[e], o);
            dp[e] += __shfl_xor_sync(0xffffffffu, dp[e], o);
        }
    }
    if (fc == 0) {
        float Ev[8], E2v[8];
#pragma unroll
        for (int e = 0; e < 8; e++) {
            int row = i0 + rw * 8 + e;
            float sb = sp[e] + ab;
            float R  = expf((ALPHA - 1.0f) * sb);
            g_Rh[row] = cvt2h(R, R);
            Ev[e]  = expf(dp[e]);
            E2v[e] = expf(ALPHA * dp[e]);
        }
        const int base2 = (i0 + rw * 8) >> 1;
#pragma unroll
        for (int p2 = 0; p2 < 4; p2++) {
            g_Epk[base2 + p2]  = cvt2h(Ev[2 * p2],  Ev[2 * p2 + 1]);
            g_E2pk[base2 + p2] = cvt2h(E2v[2 * p2], E2v[2 * p2 + 1]);
        }
    }

    // ---- transposed fp16 stores, 32-chunk INTERLEAVED order ----
    const int    jb    = (i0 & (NN - 1)) + rw * 8;
    const size_t plane = (size_t)(i0 >> 11) * FOUT;
    const int    ibase = (jb & ~31) + (((jb >> 4) & 1) << 2) + (((jb >> 3) & 1) << 1);
#pragma unroll
    for (int ff = 0; ff < 4; ff++) {
        int f = fc * 4 + ff;
        size_t rowb = (plane + f) * NN + ibase;
#pragma unroll
        for (int p2 = 0; p2 < 4; p2++) {
            float v0 = hv[p2 * 2][ff], v1 = hv[p2 * 2 + 1][ff];
            *(uint32_t*)&g_hhT[rowb + p2 * 8] = cvt2h(v0, v1);
        }
    }
}

// ============================================================================
// Kernel 2: split-K masked softmax-weight P@h via mma.sync fp16.
// p = mask * max(E_j, R_i*E2_j), computed natively in half2.
// Row-sum l via an extra ones-column MMA (no scalar accumulation).
// Grid (16, 8, SPLIT=2) x 256 threads.
// ============================================================================
#define NC (NN / 32)
#define ONE2 0x3C003C00u

__global__ __launch_bounds__(256, 2) void k_attn3(
    const int* __restrict__ adj)
{
    __shared__ __align__(16) uint8_t sBH[2][FOUT * 64];   // 2 x 4 KB
    __shared__ uint32_t sEp[2][16];
    __shared__ uint32_t sE2p[2][16];

    const int t    = threadIdx.x;
    const int wid  = t >> 5;
    const int lane = t & 31;
    const int q    = lane & 3;
    const int r    = lane >> 2;
    const int b    = blockIdx.y;
    const int i0   = blockIdx.x * 128;
    const int z    = blockIdx.z;
    const int ch0  = z * (NC / SPLIT);
    const int ch1  = ch0 + (NC / SPLIT);

    const int iA = i0 + wid * 16 + r;
    const int iB = iA + 8;
    const size_t bNN = (size_t)b * NN;

    const __half2 RA = u2h(g_Rh[bNN + iA]);
    const __half2 RB = u2h(g_Rh[bNN + iB]);
    const int* aA = adj + bNN * NN + (size_t)iA * NN + 2 * q;
    const int* aB = aA + 8 * NN;

    float c[8][4];
#pragma unroll
    for (int n = 0; n < 8; n++)
#pragma unroll
        for (int k = 0; k < 4; k++) c[n][k] = 0.0f;
    float cl[4] = {0.0f, 0.0f, 0.0f, 0.0f};    // ones-column: row sums

    const int feat = t >> 2;
    const int qg   = t & 3;
    const unsigned short* hhp = g_hhT + ((size_t)b * FOUT + feat) * NN + qg * 8;
    const uint32_t sOff = (uint32_t)feat * 64 + (uint32_t)qg * 16;
    const uint32_t ebase = (uint32_t)(bNN >> 1);

    // prologue
    *(uint4*)&sBH[0][sOff] = *(const uint4*)(hhp + ch0 * 32);
    if (t < 16)      sEp[0][t]       = g_Epk[ebase + ch0 * 16 + t];
    else if (t < 32) sE2p[0][t - 16] = g_E2pk[ebase + ch0 * 16 + (t - 16)];

    int2 mC[8];
#pragma unroll
    for (int kk = 0; kk < 2; kk++) {
        const int jo = ch0 * 32 + kk * 16;
        mC[kk * 4 + 0] = *(const int2*)(aA + jo);
        mC[kk * 4 + 1] = *(const int2*)(aA + jo + 8);
        mC[kk * 4 + 2] = *(const int2*)(aB + jo);
        mC[kk * 4 + 3] = *(const int2*)(aB + jo + 8);
    }
    __syncthreads();

    const uint32_t tb = (uint32_t)r * 64 + (uint32_t)q * 16;

    uint4 pf_h; uint32_t pf_e;
#pragma unroll 1
    for (int ch = ch0; ch < ch1; ch++) {
        const int s   = ch & 1;
        const int j0c = ch * 32;

        int2 mN[8];
        if (ch + 1 < ch1) {
            pf_h = *(const uint4*)(hhp + j0c + 32);
            if (t < 16)      pf_e = g_Epk[ebase + (ch + 1) * 16 + t];
            else if (t < 32) pf_e = g_E2pk[ebase + (ch + 1) * 16 + (t - 16)];
#pragma unroll
            for (int kk = 0; kk < 2; kk++) {
                const int jo = j0c + 32 + kk * 16;
                mN[kk * 4 + 0] = *(const int2*)(aA + jo);
                mN[kk * 4 + 1] = *(const int2*)(aA + jo + 8);
                mN[kk * 4 + 2] = *(const int2*)(aB + jo);
                mN[kk * 4 + 3] = *(const int2*)(aB + jo + 8);
            }
        }

        // ---- A fragments: p = mask * max(E, R*E2), all half2 ----
        uint32_t ah[2][4];
#pragma unroll
        for (int kk = 0; kk < 2; kk++) {
            const int pi = kk * 8 + q;
            __half2 E   = u2h(sEp[s][pi]);
            __half2 Eb  = u2h(sEp[s][pi + 4]);
            __half2 E2  = u2h(sE2p[s][pi]);
            __half2 E2b = u2h(sE2p[s][pi + 4]);

            __half2 pa0 = __hmax2(E,  __hmul2(RA, E2));
            __half2 pb0 = __hmax2(E,  __hmul2(RB, E2));
            __half2 pa1 = __hmax2(Eb, __hmul2(RA, E2b));
            __half2 pb1 = __hmax2(Eb, __hmul2(RB, E2b));

            ah[kk][0] = h2u(__hmul2(pa0, mask2(mC[kk * 4 + 0].x, mC[kk * 4 + 0].y)));
            ah[kk][1] = h2u(__hmul2(pb0, mask2(mC[kk * 4 + 2].x, mC[kk * 4 + 2].y)));
            ah[kk][2] = h2u(__hmul2(pa1, mask2(mC[kk * 4 + 1].x, mC[kk * 4 + 1].y)));
            ah[kk][3] = h2u(__hmul2(pb1, mask2(mC[kk * 4 + 3].x, mC[kk * 4 + 3].y)));
        }

        // ---- mma: 8 n-tiles + ones column for row sums ----
#pragma unroll
        for (int n = 0; n < 8; n++) {
            uint4 bh = *(const uint4*)&sBH[s][(uint32_t)n * 512 + tb];
            mma16816h(c[n], ah[0], bh.x, bh.y);
            mma16816h(c[n], ah[1], bh.z, bh.w);
        }
        mma16816h(cl, ah[0], ONE2, ONE2);
        mma16816h(cl, ah[1], ONE2, ONE2);

        if (ch + 1 < ch1) {
            *(uint4*)&sBH[s ^ 1][sOff] = pf_h;
            if (t < 16)      sEp[s ^ 1][t]       = pf_e;
            else if (t < 32) sE2p[s ^ 1][t - 16] = pf_e;
#pragma unroll
            for (int u = 0; u < 8; u++) mC[u] = mN[u];
        }
        __syncthreads();
    }

    // ---- write split-K partials; l comes straight from the ones column ----
    float* pa = g_pacc + (size_t)z * ((size_t)ROWS_TOT * FOUT);
    float* opA = pa + (bNN + iA) * FOUT + 2 * q;
    float* opB = pa + (bNN + iB) * FOUT + 2 * q;
#pragma unroll
    for (int n = 0; n < 8; n++) {
        *(float2*)(opA + n * 8) = make_float2(c[n][0], c[n][1]);
        *(float2*)(opB + n * 8) = make_float2(c[n][2], c[n][3]);
    }
    if (q == 0) {
        g_pl[(size_t)z * ROWS_TOT + bNN + iA] = cl[0];
        g_pl[(size_t)z * ROWS_TOT + bNN + iB] = cl[2];
    }
}

// ============================================================================
// Kernel 3: combine split-K partials, normalize, ELU, write output.
// ============================================================================
__global__ __launch_bounds__(256) void k_fin(float* __restrict__ out)
{
    const int idx = blockIdx.x * 256 + threadIdx.x;
    const int row = idx >> 4;
    const int fg  = (idx & 15) << 2;
    const size_t o = (size_t)row * FOUT + fg;
    const size_t PS = (size_t)ROWS_TOT * FOUT;

    float l = 0.0f;
    float4 a = make_float4(0.0f, 0.0f, 0.0f, 0.0f);
#pragma unroll
    for (int zz = 0; zz < SPLIT; zz++) {
        l += g_pl[(size_t)zz * ROWS_TOT + row];
        float4 p = *(const float4*)&g_pacc[(size_t)zz * PS + o];
        a.x += p.x; a.y += p.y; a.z += p.z; a.w += p.w;
    }
    const float li = 1.0f / l;
    float v0 = a.x * li, v1 = a.y * li, v2 = a.z * li, v3 = a.w * li;
    v0 = v0 > 0.0f ? v0 : expm1f(v0);
    v1 = v1 > 0.0f ? v1 : expm1f(v1);
    v2 = v2 > 0.0f ? v2 : expm1f(v2);
    v3 = v3 > 0.0f ? v3 : expm1f(v3);
    *(float4*)&out[o] = make_float4(v0, v1, v2, v3);
}

// ============================================================================
extern "C" void kernel_launch(void* const* d_in, const int* in_sizes, int n_in,
                              void* d_out, int out_size)
{
    const float* x     = (const float*)d_in[0];
    const int*   adj   = (const int*)d_in[1];
    const float* W     = (const float*)d_in[2];
    const float* bW    = (const float*)d_in[3];
    const float* a_src = (const float*)d_in[4];
    const float* a_dst = (const float*)d_in[5];
    const float* a_b   = (const float*)d_in[6];
    float* out = (float*)d_out;
    (void)in_sizes; (void)n_in; (void)out_size;

    cudaFuncSetAttribute(k_linear, cudaFuncAttributeMaxDynamicSharedMemorySize,
                         LIN_SMEM);

    k_linear<<<ROWS_TOT / 64, 128, LIN_SMEM>>>(x, W, bW, a_src, a_dst, a_b);

    dim3 grid(NN / 128, BB, SPLIT);
    k_attn3<<<grid, 256>>>(adj);

    k_fin<<<(ROWS_TOT * 16) / 256, 256>>>(out);
}

// round 17
// speedup vs baseline: 1.1491x; 1.0711x over previous
#include <cuda_runtime.h>
#include <cuda_fp16.h>
#include <cstdint>
#include <cstddef>

#define BB   8
#define NN   2048
#define FIN  256
#define FOUT 64
#define ALPHA 0.2f
#define SPLIT 2
#define ROWS_TOT (BB * NN)

// ---------------- scratch (device globals: allocation-free) ----------------
__device__ uint32_t g_Rh[ROWS_TOT];        // half2(R_i, R_i), R = exp((a-1)sb)
__device__ uint32_t g_Epk[ROWS_TOT / 2];   // half2(E_{2p}, E_{2p+1})
__device__ uint32_t g_E2pk[ROWS_TOT / 2];  // half2(E2_{2p}, E2_{2p+1})
// h transposed fp16, [b][feat][j], j 32-chunk interleaved:
//   pos(j) = (j&~31) + ((j>>2)&3)*8 + ((j>>4)&1)*4 + (j&3)
__device__ unsigned short g_hhT[BB * FOUT * NN];
__device__ float g_pacc[SPLIT * ROWS_TOT * FOUT];    // 8 MB split-K partials
__device__ float g_pl[SPLIT * ROWS_TOT];
__device__ uint32_t g_WH[8192];            // W fragment-order fp16 hi
__device__ uint32_t g_WL[8192];            // W fragment-order fp16 lo residual

// ---------------- helpers ----------------
static __device__ __forceinline__ uint32_t cvt2h(float lo, float hi) {
    uint32_t d;
    asm("cvt.rn.f16x2.f32 %0, %1, %2;" : "=r"(d) : "f"(hi), "f"(lo));
    return d;
}
static __device__ __forceinline__ float h_lo(uint32_t w) {
    return __half2float(__ushort_as_half((unsigned short)(w & 0xffffu)));
}
static __device__ __forceinline__ float h_hi(uint32_t w) {
    return __half2float(__ushort_as_half((unsigned short)(w >> 16)));
}
static __device__ __forceinline__ __half2 u2h(uint32_t u) {
    __half2 h; *(uint32_t*)&h = u; return h;
}
static __device__ __forceinline__ uint32_t h2u(__half2 h) {
    return *(uint32_t*)&h;
}
// mask half2 (1.0/0.0) from two 0/1 ints
static __device__ __forceinline__ __half2 mask2(int mx, int my) {
    uint32_t r;
    asm("prmt.b32 %0, %1, %2, 0x5410;" : "=r"(r) : "r"(mx), "r"(my));
    return __hgt2(u2h(r), u2h(0u));
}

static __device__ __forceinline__ void mma16816h(float* c, const uint32_t* a,
                                                 uint32_t b0, uint32_t b1) {
    asm volatile(
        "mma.sync.aligned.m16n8k16.row.col.f32.f16.f16.f32 "
        "{%0,%1,%2,%3}, {%4,%5,%6,%7}, {%8,%9}, {%0,%1,%2,%3};"
        : "+f"(c[0]), "+f"(c[1]), "+f"(c[2]), "+f"(c[3])
        : "r"(a[0]), "r"(a[1]), "r"(a[2]), "r"(a[3]), "r"(b0), "r"(b1));
}

// ============================================================================
// Kernel 0: one-shot W prepack into fragment-order fp16 hi/lo (global).
// ============================================================================
__global__ __launch_bounds__(128) void k_wpk(const float* __restrict__ W)
{
    const int t = threadIdx.x;
#pragma unroll
    for (int i = 0; i < 8; i++) {
        int u    = blockIdx.x * 1024 + t + 128 * i;
        int half = u & 1;
        int qq   = (u >> 1) & 3;
        int n    = (u >> 3) & 63;
        int ks   = u >> 9;
        int k0   = ks * 16 + half * 8 + 2 * qq;
        float w0 = W[(size_t)k0 * FOUT + n];
        float w1 = W[(size_t)(k0 + 1) * FOUT + n];
        uint32_t hi = cvt2h(w0, w1);
        g_WH[u] = hi;
        g_WL[u] = cvt2h(w0 - h_lo(hi), w1 - h_hi(hi));
    }
}

// ============================================================================
// Kernel 1: h = x @ W + b_W via mma.sync fp16 (2-term: ah*bh + ah*bl).
// 128 threads, 64 rows/CTA, grid 256. W fragments copied from g_WH/g_WL.
// Epilogue writes half2 tables + transposed fp16 h (interleaved order).
// ============================================================================
#define LIN_SW_BYTES 32768
#define LIN_HB_STRIDE 68
#define LIN_SMEM (2 * LIN_SW_BYTES)

__global__ __launch_bounds__(128, 3) void k_linear(
    const float* __restrict__ x, const float* __restrict__ bW,
    const float* __restrict__ a_src, const float* __restrict__ a_dst,
    const float* __restrict__ a_b)
{
    extern __shared__ __align__(16) unsigned char lsm[];
    uint32_t* WH32 = (uint32_t*)lsm;
    uint32_t* WL32 = (uint32_t*)(lsm + LIN_SW_BYTES);
    float*    hbuf = (float*)lsm;                     // alias (post-mainloop)

    const int t    = threadIdx.x;
    const int w    = t >> 5;
    const int lane = t & 31;
    const int q    = lane & 3;
    const int r    = lane >> 2;
    const int i0   = blockIdx.x * 64;
    const float ab = a_b[0];

    // ---- copy prepacked W fragments (uint4) ----
#pragma unroll
    for (int i = 0; i < 16; i++) {
        ((uint4*)WH32)[t + 128 * i] = ((const uint4*)g_WH)[t + 128 * i];
        ((uint4*)WL32)[t + 128 * i] = ((const uint4*)g_WL)[t + 128 * i];
    }
    __syncthreads();

    const float* xA = x + (size_t)(i0 + w * 16 + r) * FIN;
    const float* xB = xA + (size_t)8 * FIN;

    float c[8][4];
#pragma unroll
    for (int n = 0; n < 8; n++)
#pragma unroll
        for (int k = 0; k < 4; k++) c[n][k] = 0.0f;

    float2 xb[2][4];
    xb[0][0] = *(const float2*)(xA + 2 * q);
    xb[0][1] = *(const float2*)(xB + 2 * q);
    xb[0][2] = *(const float2*)(xA + 8 + 2 * q);
    xb[0][3] = *(const float2*)(xB + 8 + 2 * q);

#pragma unroll
    for (int ks = 0; ks < 16; ks++) {
        const int cur = ks & 1;
        if (ks + 1 < 16) {
            const int kb = (ks + 1) * 16;
            xb[cur ^ 1][0] = *(const float2*)(xA + kb + 2 * q);
            xb[cur ^ 1][1] = *(const float2*)(xB + kb + 2 * q);
            xb[cur ^ 1][2] = *(const float2*)(xA + kb + 8 + 2 * q);
            xb[cur ^ 1][3] = *(const float2*)(xB + kb + 8 + 2 * q);
        }

        uint32_t ah[4];
#pragma unroll
        for (int e = 0; e < 4; e++) {
            float2 xv = xb[cur][e];
            ah[e] = cvt2h(xv.x, xv.y);
        }

#pragma unroll
        for (int nt = 0; nt < 8; nt++) {
            int slot = (ks * 64 + nt * 8 + r) * 4 + q;
            uint2 bh = *(const uint2*)&WH32[slot * 2];
            uint2 bl = *(const uint2*)&WL32[slot * 2];
            mma16816h(c[nt], ah, bh.x, bh.y);
            mma16816h(c[nt], ah, bl.x, bl.y);
        }
    }

    // ---- stash c to (aliased) smem ----
    __syncthreads();
    {
        float* hbA = hbuf + (w * 16 + r) * LIN_HB_STRIDE;
        float* hbB = hbA + 8 * LIN_HB_STRIDE;
#pragma unroll
        for (int nt = 0; nt < 8; nt++) {
            *(float2*)(hbA + nt * 8 + 2 * q) = make_float2(c[nt][0], c[nt][1]);
            *(float2*)(hbB + nt * 8 + 2 * q) = make_float2(c[nt][2], c[nt][3]);
        }
    }
    __syncthreads();

    // ---- epilogue ----
    const int fc = t & 15;
    const int rw = t >> 4;
    float4 bw4 = *(const float4*)&bW[fc * 4];
    float4 as4 = *(const float4*)&a_src[fc * 4];
    float4 ad4 = *(const float4*)&a_dst[fc * 4];

    float hv[8][4];
    float sp[8], dp[8];
#pragma unroll
    for (int e = 0; e < 8; e++) {
        float4 v = *(const float4*)&hbuf[(rw * 8 + e) * LIN_HB_STRIDE + fc * 4];
        hv[e][0] = v.x + bw4.x; hv[e][1] = v.y + bw4.y;
        hv[e][2] = v.z + bw4.z; hv[e][3] = v.w + bw4.w;
        sp[e] = hv[e][0] * as4.x + hv[e][1] * as4.y + hv[e][2] * as4.z + hv[e][3] * as4.w;
        dp[e] = hv[e][0] * ad4.x + hv[e][1] * ad4.y + hv[e][2] * ad4.z + hv[e][3] * ad4.w;
    }
#pragma unroll
    for (int o = 1; o < 16; o <<= 1) {
#pragma unroll
        for (int e = 0; e < 8; e++) {
            sp[e] += __shfl_xor_sync(0xffffffffu, sp[e], o);
            dp[e] += __shfl_xor_sync(0xffffffffu, dp[e], o);
        }
    }
    if (fc == 0) {
        float Ev[8], E2v[8];
#pragma unroll
        for (int e = 0; e < 8; e++) {
            int row = i0 + rw * 8 + e;
            float sb = sp[e] + ab;
            float R  = expf((ALPHA - 1.0f) * sb);
            g_Rh[row] = cvt2h(R, R);
            Ev[e]  = expf(dp[e]);
            E2v[e] = expf(ALPHA * dp[e]);
        }
        const int base2 = (i0 + rw * 8) >> 1;
#pragma unroll
        for (int p2 = 0; p2 < 4; p2++) {
            g_Epk[base2 + p2]  = cvt2h(Ev[2 * p2],  Ev[2 * p2 + 1]);
            g_E2pk[base2 + p2] = cvt2h(E2v[2 * p2], E2v[2 * p2 + 1]);
        }
    }

    // ---- transposed fp16 stores, interleaved order ----
    // rows jb..jb+7 (jb mult of 8): pos = (jb&~31) + ((jb>>2)&3)*8 + kk*4 + e
    // for e=0..3, and the e=4..7 run lands at +8 (next q-group).
    const int    jb    = (i0 & (NN - 1)) + rw * 8;
    const size_t plane = (size_t)(i0 >> 11) * FOUT;
    const int    kk    = (jb >> 4) & 1;
    const int    base  = (jb & ~31) + (((jb >> 2) & 3) << 3) + kk * 4;
#pragma unroll
    for (int ff = 0; ff < 4; ff++) {
        int f = fc * 4 + ff;
        size_t rowb = (plane + f) * NN + base;
        uint2 w01 = make_uint2(cvt2h(hv[0][ff], hv[1][ff]),
                               cvt2h(hv[2][ff], hv[3][ff]));
        uint2 w23 = make_uint2(cvt2h(hv[4][ff], hv[5][ff]),
                               cvt2h(hv[6][ff], hv[7][ff]));
        *(uint2*)&g_hhT[rowb]     = w01;
        *(uint2*)&g_hhT[rowb + 8] = w23;
    }
}

// ============================================================================
// Kernel 2: split-K masked softmax-weight P@h via mma.sync fp16.
// j-permutation: lane q's k-slots {2q,2q+1,2q+8,2q+9} <-> j {4q..4q+3}.
// adj: 4x LDG.128 per chunk; E tables: LDS.64 per (kk, table).
// ============================================================================
#define NC (NN / 32)
#define ONE2 0x3C003C00u

__global__ __launch_bounds__(256, 2) void k_attn3(
    const int* __restrict__ adj)
{
    __shared__ __align__(16) uint8_t sBH[2][FOUT * 64];   // 2 x 4 KB
    __shared__ __align__(8) uint32_t sEp[2][16];
    __shared__ __align__(8) uint32_t sE2p[2][16];

    const int t    = threadIdx.x;
    const int wid  = t >> 5;
    const int lane = t & 31;
    const int q    = lane & 3;
    const int r    = lane >> 2;
    const int b    = blockIdx.y;
    const int i0   = blockIdx.x * 128;
    const int z    = blockIdx.z;
    const int ch0  = z * (NC / SPLIT);
    const int ch1  = ch0 + (NC / SPLIT);

    const int iA = i0 + wid * 16 + r;
    const int iB = iA + 8;
    const size_t bNN = (size_t)b * NN;

    const __half2 RA = u2h(g_Rh[bNN + iA]);
    const __half2 RB = u2h(g_Rh[bNN + iB]);
    const int* aA = adj + bNN * NN + (size_t)iA * NN + 4 * q;
    const int* aB = aA + 8 * NN;

    float c[8][4];
#pragma unroll
    for (int n = 0; n < 8; n++)
#pragma unroll
        for (int k = 0; k < 4; k++) c[n][k] = 0.0f;
    float cl[4] = {0.0f, 0.0f, 0.0f, 0.0f};    // ones-column: row sums

    const int feat = t >> 2;
    const int qg   = t & 3;
    const unsigned short* hhp = g_hhT + ((size_t)b * FOUT + feat) * NN + qg * 8;
    const uint32_t sOff = (uint32_t)feat * 64 + (uint32_t)qg * 16;
    const uint32_t ebase = (uint32_t)(bNN >> 1);

    // prologue
    *(uint4*)&sBH[0][sOff] = *(const uint4*)(hhp + ch0 * 32);
    if (t < 16)      sEp[0][t]       = g_Epk[ebase + ch0 * 16 + t];
    else if (t < 32) sE2p[0][t - 16] = g_E2pk[ebase + ch0 * 16 + (t - 16)];

    int4 mC[4];
#pragma unroll
    for (int kk = 0; kk < 2; kk++) {
        const int jo = ch0 * 32 + kk * 16;
        mC[kk * 2 + 0] = *(const int4*)(aA + jo);
        mC[kk * 2 + 1] = *(const int4*)(aB + jo);
    }
    __syncthreads();

    const uint32_t tb = (uint32_t)r * 64 + (uint32_t)q * 16;

    uint4 pf_h; uint32_t pf_e;
#pragma unroll 1
    for (int ch = ch0; ch < ch1; ch++) {
        const int s   = ch & 1;
        const int j0c = ch * 32;

        int4 mN[4];
        if (ch + 1 < ch1) {
            pf_h = *(const uint4*)(hhp + j0c + 32);
            if (t < 16)      pf_e = g_Epk[ebase + (ch + 1) * 16 + t];
            else if (t < 32) pf_e = g_E2pk[ebase + (ch + 1) * 16 + (t - 16)];
#pragma unroll
            for (int kk = 0; kk < 2; kk++) {
                const int jo = j0c + 32 + kk * 16;
                mN[kk * 2 + 0] = *(const int4*)(aA + jo);
                mN[kk * 2 + 1] = *(const int4*)(aB + jo);
            }
        }

        // ---- A fragments: p = mask * max(E, R*E2), all half2 ----
        uint32_t ah[2][4];
#pragma unroll
        for (int kk = 0; kk < 2; kk++) {
            uint2 Eu  = *(const uint2*)&sEp[s][kk * 8 + 2 * q];
            uint2 E2u = *(const uint2*)&sE2p[s][kk * 8 + 2 * q];
            __half2 E0  = u2h(Eu.x),  E1  = u2h(Eu.y);
            __half2 E20 = u2h(E2u.x), E21 = u2h(E2u.y);

            __half2 pa0 = __hmax2(E0, __hmul2(RA, E20));
            __half2 pa1 = __hmax2(E1, __hmul2(RA, E21));
            __half2 pb0 = __hmax2(E0, __hmul2(RB, E20));
            __half2 pb1 = __hmax2(E1, __hmul2(RB, E21));

            const int4 mA = mC[kk * 2 + 0];
            const int4 mB = mC[kk * 2 + 1];
            ah[kk][0] = h2u(__hmul2(pa0, mask2(mA.x, mA.y)));
            ah[kk][2] = h2u(__hmul2(pa1, mask2(mA.z, mA.w)));
            ah[kk][1] = h2u(__hmul2(pb0, mask2(mB.x, mB.y)));
            ah[kk][3] = h2u(__hmul2(pb1, mask2(mB.z, mB.w)));
        }

        // ---- mma: 8 n-tiles + ones column for row sums ----
#pragma unroll
        for (int n = 0; n < 8; n++) {
            uint4 bh = *(const uint4*)&sBH[s][(uint32_t)n * 512 + tb];
            mma16816h(c[n], ah[0], bh.x, bh.y);
            mma16816h(c[n], ah[1], bh.z, bh.w);
        }
        mma16816h(cl, ah[0], ONE2, ONE2);
        mma16816h(cl, ah[1], ONE2, ONE2);

        if (ch + 1 < ch1) {
            *(uint4*)&sBH[s ^ 1][sOff] = pf_h;
            if (t < 16)      sEp[s ^ 1][t]       = pf_e;
            else if (t < 32) sE2p[s ^ 1][t - 16] = pf_e;
#pragma unroll
            for (int u = 0; u < 4; u++) mC[u] = mN[u];
        }
        __syncthreads();
    }

    // ---- write split-K partials; l from the ones column ----
    float* pa = g_pacc + (size_t)z * ((size_t)ROWS_TOT * FOUT);
    float* opA = pa + (bNN + iA) * FOUT + 2 * q;
    float* opB = pa + (bNN + iB) * FOUT + 2 * q;
#pragma unroll
    for (int n = 0; n < 8; n++) {
        *(float2*)(opA + n * 8) = make_float2(c[n][0], c[n][1]);
        *(float2*)(opB + n * 8) = make_float2(c[n][2], c[n][3]);
    }
    if (q == 0) {
        g_pl[(size_t)z * ROWS_TOT + bNN + iA] = cl[0];
        g_pl[(size_t)z * ROWS_TOT + bNN + iB] = cl[2];
    }
}

// ============================================================================
// Kernel 3: combine split-K partials, normalize, ELU, write output.
// ============================================================================
__global__ __launch_bounds__(256) void k_fin(float* __restrict__ out)
{
    const int idx = blockIdx.x * 256 + threadIdx.x;
    const int row = idx >> 4;
    const int fg  = (idx & 15) << 2;
    const size_t o = (size_t)row * FOUT + fg;
    const size_t PS = (size_t)ROWS_TOT * FOUT;

    float l = 0.0f;
    float4 a = make_float4(0.0f, 0.0f, 0.0f, 0.0f);
#pragma unroll
    for (int zz = 0; zz < SPLIT; zz++) {
        l += g_pl[(size_t)zz * ROWS_TOT + row];
        float4 p = *(const float4*)&g_pacc[(size_t)zz * PS + o];
        a.x += p.x; a.y += p.y; a.z += p.z; a.w += p.w;
    }
    const float li = 1.0f / l;
    float v0 = a.x * li, v1 = a.y * li, v2 = a.z * li, v3 = a.w * li;
    v0 = v0 > 0.0f ? v0 : expm1f(v0);
    v1 = v1 > 0.0f ? v1 : expm1f(v1);
    v2 = v2 > 0.0f ? v2 : expm1f(v2);
    v3 = v3 > 0.0f ? v3 : expm1f(v3);
    *(float4*)&out[o] = make_float4(v0, v1, v2, v3);
}

// ============================================================================
extern "C" void kernel_launch(void* const* d_in, const int* in_sizes, int n_in,
                              void* d_out, int out_size)
{
    const float* x     = (const float*)d_in[0];
    const int*   adj   = (const int*)d_in[1];
    const float* W     = (const float*)d_in[2];
    const float* bW    = (const float*)d_in[3];
    const float* a_src = (const float*)d_in[4];
    const float* a_dst = (const float*)d_in[5];
    const float* a_b   = (const float*)d_in[6];
    float* out = (float*)d_out;
    (void)in_sizes; (void)n_in; (void)out_size;

    cudaFuncSetAttribute(k_linear, cudaFuncAttributeMaxDynamicSharedMemorySize,
                         LIN_SMEM);

    k_wpk<<<8, 128>>>(W);
    k_linear<<<ROWS_TOT / 64, 128, LIN_SMEM>>>(x, bW, a_src, a_dst, a_b);

    dim3 grid(NN / 128, BB, SPLIT);
    k_attn3<<<grid, 256>>>(adj);

    k_fin<<<(ROWS_TOT * 16) / 256, 256>>>(out);
}